// round 8
// baseline (speedup 1.0000x reference)
#include <cuda_runtime.h>

#define N_NODES 100000
#define N_EDGES 1200000
#define F_IN 128
#define F_HID 256
#define F_OUT 40

// Scratch (static device globals — allocation-free per harness rules)
__device__ __align__(16) float g_deg[N_NODES];
__device__ __align__(16) float g_dinv[N_NODES];
__device__ __align__(16) float g_ag1[(size_t)N_NODES * F_IN];   // A @ x
__device__ __align__(16) float g_h  [(size_t)N_NODES * F_HID];  // relu(ag1@W1+b1)
__device__ __align__(16) float g_h2 [(size_t)N_NODES * F_OUT];  // h @ W2

// ---------------- degree / norm ----------------

__global__ void k_deg_init() {
    int i = blockIdx.x * blockDim.x + threadIdx.x;
    if (i < N_NODES) g_deg[i] = 1.0f;  // self-loop
}

__global__ void k_deg_count(const int* __restrict__ ei) {
    int e = blockIdx.x * blockDim.x + threadIdx.x;
    if (e >= N_EDGES) return;
    unsigned c = (unsigned)ei[N_EDGES + e];
    if (c < N_NODES) atomicAdd(&g_deg[c], 1.0f);
}

__global__ void k_dinv() {
    int i = blockIdx.x * blockDim.x + threadIdx.x;
    if (i < N_NODES) g_dinv[i] = rsqrtf(g_deg[i]);
}

// ---------------- layer 1 propagation: ag1 = A @ x ----------------

__global__ void k_init_ag1(const float* __restrict__ x) {
    int idx = blockIdx.x * blockDim.x + threadIdx.x;  // N*32 float4 chunks
    if (idx >= N_NODES * 32) return;
    int i = idx >> 5;
    float s = g_dinv[i]; s *= s;
    float4 v = ((const float4*)x)[idx];
    ((float4*)g_ag1)[idx] = make_float4(v.x * s, v.y * s, v.z * s, v.w * s);
}

__global__ void k_prop1(const int* __restrict__ ei, const float* __restrict__ x) {
    int gid = blockIdx.x * blockDim.x + threadIdx.x;
    int e = gid >> 5;
    if (e >= N_EDGES) return;
    int lane = gid & 31;
    unsigned r = (unsigned)ei[e];
    unsigned c = (unsigned)ei[N_EDGES + e];
    if (r >= N_NODES || c >= N_NODES) return;
    float nrm = g_dinv[r] * g_dinv[c];
    float4 v = ((const float4*)(x + (size_t)r * F_IN))[lane];
    float* dst = g_ag1 + (size_t)c * F_IN + lane * 4;
    atomicAdd(dst + 0, v.x * nrm);
    atomicAdd(dst + 1, v.y * nrm);
    atomicAdd(dst + 2, v.z * nrm);
    atomicAdd(dst + 3, v.w * nrm);
}

// ---------------- tf32x3 tensor-core GEMM ----------------
// C = A @ B (+bias)(+relu), fp32 in/out, tf32 split hi/lo, 3 MMA passes:
// Ah*Bh + Ah*Bl + Al*Bh  -> ~1e-6 relative error.

__device__ __forceinline__ float tf32r(float x) {
    float r; asm("cvt.rna.tf32.f32 %0, %1;" : "=f"(r) : "f"(x)); return r;
}

__device__ __forceinline__ void mma_tf32(float c[4], const float a[4], const float b[2]) {
    asm volatile(
        "mma.sync.aligned.m16n8k8.row.col.f32.tf32.tf32.f32 "
        "{%0,%1,%2,%3},{%4,%5,%6,%7},{%8,%9},{%0,%1,%2,%3};"
        : "+f"(c[0]), "+f"(c[1]), "+f"(c[2]), "+f"(c[3])
        : "r"(__float_as_uint(a[0])), "r"(__float_as_uint(a[1])),
          "r"(__float_as_uint(a[2])), "r"(__float_as_uint(a[3])),
          "r"(__float_as_uint(b[0])), "r"(__float_as_uint(b[1])));
}

// BM=64, BN=64, BK=32, 256 threads = 8 warps (2 in M x 4 in N), warp tile 32x16.
template <int KTOT, int NTOT, bool BIAS, bool RELU>
__device__ __forceinline__ void tc_gemm(const float* __restrict__ A,
                                        const float* __restrict__ B,
                                        const float* __restrict__ bias,
                                        float* __restrict__ C, int M) {
    constexpr int BM = 64, BN = 64, BK = 32;
    constexpr int ASTR = 36, BSTR = 68;  // padded strides -> conflict-free frags
    __shared__ float Ah[BM * ASTR], Al[BM * ASTR];
    __shared__ float Bh[BK * BSTR], Bl[BK * BSTR];

    const int t = threadIdx.x, lane = t & 31, wid = t >> 5;
    const int wm = wid & 1, wn = wid >> 1;
    const int m0 = blockIdx.x * BM, n0 = blockIdx.y * BN;

    float c[2][2][4] = {};

    for (int kk = 0; kk < KTOT; kk += BK) {
        // A tile: 64x32 = 512 float4, 2 per thread
        #pragma unroll
        for (int i = 0; i < 2; i++) {
            int f = t + i * 256;
            int m = f >> 3, k4 = f & 7;
            float4 v = make_float4(0.f, 0.f, 0.f, 0.f);
            if (m0 + m < M)
                v = *(const float4*)(A + (size_t)(m0 + m) * KTOT + kk + k4 * 4);
            int p = m * ASTR + k4 * 4;
            float h;
            h = tf32r(v.x); Ah[p + 0] = h; Al[p + 0] = tf32r(v.x - h);
            h = tf32r(v.y); Ah[p + 1] = h; Al[p + 1] = tf32r(v.y - h);
            h = tf32r(v.z); Ah[p + 2] = h; Al[p + 2] = tf32r(v.z - h);
            h = tf32r(v.w); Ah[p + 3] = h; Al[p + 3] = tf32r(v.w - h);
        }
        // B tile: 32x64 = 512 float4, 2 per thread (zero-pad past NTOT)
        #pragma unroll
        for (int i = 0; i < 2; i++) {
            int f = t + i * 256;
            int k = f >> 4, n4 = f & 15;
            float4 v = make_float4(0.f, 0.f, 0.f, 0.f);
            if (n0 + n4 * 4 + 3 < NTOT)
                v = *(const float4*)(B + (size_t)(kk + k) * NTOT + n0 + n4 * 4);
            int p = k * BSTR + n4 * 4;
            float h;
            h = tf32r(v.x); Bh[p + 0] = h; Bl[p + 0] = tf32r(v.x - h);
            h = tf32r(v.y); Bh[p + 1] = h; Bl[p + 1] = tf32r(v.y - h);
            h = tf32r(v.z); Bh[p + 2] = h; Bl[p + 2] = tf32r(v.z - h);
            h = tf32r(v.w); Bh[p + 3] = h; Bl[p + 3] = tf32r(v.w - h);
        }
        __syncthreads();

        #pragma unroll
        for (int ks = 0; ks < BK / 8; ks++) {
            const int k0 = ks * 8;
            float ah[2][4], al[2][4], bh[2][2], bl[2][2];
            const int ar = wm * 32 + (lane >> 2);
            const int ac = k0 + (lane & 3);
            #pragma unroll
            for (int i = 0; i < 2; i++) {
                int base = (ar + i * 16) * ASTR + ac;
                ah[i][0] = Ah[base];             al[i][0] = Al[base];
                ah[i][1] = Ah[base + 8 * ASTR];  al[i][1] = Al[base + 8 * ASTR];
                ah[i][2] = Ah[base + 4];         al[i][2] = Al[base + 4];
                ah[i][3] = Ah[base + 8 * ASTR + 4]; al[i][3] = Al[base + 8 * ASTR + 4];
            }
            const int br = k0 + (lane & 3);
            const int bc = wn * 16 + (lane >> 2);
            #pragma unroll
            for (int j = 0; j < 2; j++) {
                int base = br * BSTR + bc + j * 8;
                bh[j][0] = Bh[base];             bl[j][0] = Bl[base];
                bh[j][1] = Bh[base + 4 * BSTR];  bl[j][1] = Bl[base + 4 * BSTR];
            }
            #pragma unroll
            for (int i = 0; i < 2; i++)
                #pragma unroll
                for (int j = 0; j < 2; j++) {
                    mma_tf32(c[i][j], ah[i], bh[j]);
                    mma_tf32(c[i][j], ah[i], bl[j]);
                    mma_tf32(c[i][j], al[i], bh[j]);
                }
        }
        __syncthreads();
    }

    // epilogue: each lane holds (c0,c1) @ row r0, (c2,c3) @ row r0+8, cols col,col+1
    #pragma unroll
    for (int i = 0; i < 2; i++) {
        int r0 = m0 + wm * 32 + i * 16 + (lane >> 2);
        #pragma unroll
        for (int j = 0; j < 2; j++) {
            int col = n0 + wn * 16 + j * 8 + 2 * (lane & 3);
            if (col < NTOT) {  // NTOT even & col even -> col+1 also in range
                float b0 = 0.f, b1 = 0.f;
                if (BIAS) { b0 = bias[col]; b1 = bias[col + 1]; }
                float v0 = c[i][j][0] + b0, v1 = c[i][j][1] + b1;
                float v2 = c[i][j][2] + b0, v3 = c[i][j][3] + b1;
                if (RELU) {
                    v0 = fmaxf(v0, 0.f); v1 = fmaxf(v1, 0.f);
                    v2 = fmaxf(v2, 0.f); v3 = fmaxf(v3, 0.f);
                }
                if (r0 < M) {
                    float2 s = make_float2(v0, v1);
                    *(float2*)(C + (size_t)r0 * NTOT + col) = s;
                }
                if (r0 + 8 < M) {
                    float2 s = make_float2(v2, v3);
                    *(float2*)(C + (size_t)(r0 + 8) * NTOT + col) = s;
                }
            }
        }
    }
}

__global__ void k_gemm1(const float* __restrict__ W1, const float* __restrict__ b1) {
    tc_gemm<F_IN, F_HID, true, true>(g_ag1, W1, b1, g_h, N_NODES);
}

__global__ void k_gemm2(const float* __restrict__ W2) {
    tc_gemm<F_HID, F_OUT, false, false>(g_h, W2, nullptr, g_h2, N_NODES);
}

// ---------------- layer 2 propagation: out = A @ h2 + b2 ----------------

__global__ void k_init_out(const float* __restrict__ b2, float* __restrict__ out) {
    int idx = blockIdx.x * blockDim.x + threadIdx.x;  // N*10 float4 chunks
    if (idx >= N_NODES * 10) return;
    int i = idx / 10;
    int c = idx % 10;
    float s = g_dinv[i]; s *= s;
    float4 h = ((const float4*)g_h2)[idx];
    float4 b = ((const float4*)b2)[c];
    ((float4*)out)[idx] = make_float4(b.x + h.x * s, b.y + h.y * s,
                                      b.z + h.z * s, b.w + h.w * s);
}

__global__ void k_prop2(const int* __restrict__ ei, float* __restrict__ out) {
    int idx = blockIdx.x * blockDim.x + threadIdx.x;
    if (idx >= N_EDGES * 10) return;
    int e = idx / 10;
    int c = idx % 10;
    unsigned r  = (unsigned)ei[e];
    unsigned cl = (unsigned)ei[N_EDGES + e];
    if (r >= N_NODES || cl >= N_NODES) return;
    float nrm = g_dinv[r] * g_dinv[cl];
    float4 v = ((const float4*)(g_h2 + (size_t)r * F_OUT))[c];
    float* dst = out + (size_t)cl * F_OUT + c * 4;
    atomicAdd(dst + 0, v.x * nrm);
    atomicAdd(dst + 1, v.y * nrm);
    atomicAdd(dst + 2, v.z * nrm);
    atomicAdd(dst + 3, v.w * nrm);
}

// ---------------- launch ----------------

extern "C" void kernel_launch(void* const* d_in, const int* in_sizes, int n_in,
                              void* d_out, int out_size) {
    const float* x  = (const float*)d_in[0];
    const int*   ei = (const int*)d_in[1];
    const float* W1 = (const float*)d_in[2];
    const float* b1 = (const float*)d_in[3];
    const float* W2 = (const float*)d_in[4];
    const float* b2 = (const float*)d_in[5];
    float*       out = (float*)d_out;

    k_deg_init <<<(N_NODES + 255) / 256, 256>>>();
    k_deg_count<<<(N_EDGES + 255) / 256, 256>>>(ei);
    k_dinv     <<<(N_NODES + 255) / 256, 256>>>();

    k_init_ag1 <<<(N_NODES * 32 + 255) / 256, 256>>>(x);
    k_prop1    <<<(N_EDGES * 32 + 255) / 256, 256>>>(ei, x);

    k_gemm1    <<<dim3((N_NODES + 63) / 64, F_HID / 64), 256>>>(W1, b1);
    k_gemm2    <<<dim3((N_NODES + 63) / 64, 1), 256>>>(W2);

    k_init_out <<<(N_NODES * 10 + 255) / 256, 256>>>(b2, out);
    k_prop2    <<<(N_EDGES * 10 + 255) / 256, 256>>>(ei, out);
}

// round 9
// speedup vs baseline: 1.9173x; 1.9173x over previous
#include <cuda_runtime.h>

#define N_NODES 100000
#define N_EDGES 1200000
#define F_IN 128
#define F_HID 256
#define F_OUT 40

#define SCAN_B 512
#define NB1 196  // ceil(100000/512)

// Scratch (static device globals — allocation-free per harness rules)
__device__ __align__(16) float g_dinv[N_NODES];
__device__ __align__(16) int   g_cnt[N_NODES];
__device__ __align__(16) int   g_rowptr[N_NODES + 1];
__device__ __align__(16) int   g_cursor[N_NODES];
__device__ __align__(16) int   g_srcs[N_EDGES];
__device__ __align__(16) int   g_blksum[NB1];
__device__ __align__(16) int   g_blkoff[NB1];
__device__ __align__(16) float g_ag1[(size_t)N_NODES * F_IN];   // A @ x
__device__ __align__(16) float g_h  [(size_t)N_NODES * F_HID];  // relu(ag1@W1+b1)
__device__ __align__(16) float g_h2 [(size_t)N_NODES * F_OUT];  // h @ W2

// ---------------- CSR build (counting sort by destination) ----------------

__global__ void k_zero() {
    int i = blockIdx.x * blockDim.x + threadIdx.x;
    if (i < N_NODES) g_cnt[i] = 0;
}

__global__ void k_count(const int* __restrict__ ei) {
    int e = blockIdx.x * blockDim.x + threadIdx.x;
    if (e >= N_EDGES) return;
    unsigned c = (unsigned)ei[N_EDGES + e];
    if (c < N_NODES) atomicAdd(&g_cnt[c], 1);
}

// per-block sums of g_cnt
__global__ void k_scan1() {
    __shared__ int sh[SCAN_B / 32];
    int t = threadIdx.x;
    int i = blockIdx.x * SCAN_B + t;
    int v = (i < N_NODES) ? g_cnt[i] : 0;
    #pragma unroll
    for (int o = 16; o; o >>= 1) v += __shfl_down_sync(~0u, v, o);
    if ((t & 31) == 0) sh[t >> 5] = v;
    __syncthreads();
    if (t < SCAN_B / 32) {
        int s = sh[t];
        #pragma unroll
        for (int o = SCAN_B / 64; o; o >>= 1) s += __shfl_down_sync((1u << (SCAN_B / 32)) - 1, s, o);
        if (t == 0) g_blksum[blockIdx.x] = s;
    }
}

// exclusive scan of NB1 (<=256) block sums, single block of 256
__global__ void k_scan2() {
    __shared__ int ws[8];
    int t = threadIdx.x;
    int v = (t < NB1) ? g_blksum[t] : 0;
    int lane = t & 31, w = t >> 5;
    int inc = v;
    #pragma unroll
    for (int o = 1; o < 32; o <<= 1) {
        int u = __shfl_up_sync(~0u, inc, o);
        if (lane >= o) inc += u;
    }
    if (lane == 31) ws[w] = inc;
    __syncthreads();
    if (t < 8) {
        int s = ws[t];
        int i2 = s;
        #pragma unroll
        for (int o = 1; o < 8; o <<= 1) {
            int u = __shfl_up_sync(0xff, i2, o);
            if (t >= o) i2 += u;
        }
        ws[t] = i2 - s;  // exclusive warp offset
    }
    __syncthreads();
    if (t < NB1) g_blkoff[t] = inc - v + ws[w];
}

// per-block exclusive scan + global offset -> rowptr, cursor, dinv
__global__ void k_scan3() {
    __shared__ int ws[SCAN_B / 32];
    int t = threadIdx.x;
    int i = blockIdx.x * SCAN_B + t;
    int v = (i < N_NODES) ? g_cnt[i] : 0;
    int lane = t & 31, w = t >> 5;
    int inc = v;
    #pragma unroll
    for (int o = 1; o < 32; o <<= 1) {
        int u = __shfl_up_sync(~0u, inc, o);
        if (lane >= o) inc += u;
    }
    if (lane == 31) ws[w] = inc;
    __syncthreads();
    if (t < SCAN_B / 32) {
        int s = ws[t];
        int i2 = s;
        #pragma unroll
        for (int o = 1; o < SCAN_B / 32; o <<= 1) {
            int u = __shfl_up_sync((1u << (SCAN_B / 32)) - 1, i2, o);
            if (t >= o) i2 += u;
        }
        ws[t] = i2 - s;
    }
    __syncthreads();
    if (i < N_NODES) {
        int excl = inc - v + ws[w] + g_blkoff[blockIdx.x];
        g_rowptr[i] = excl;
        g_cursor[i] = excl;
        g_dinv[i] = rsqrtf((float)(v + 1));  // +1 self-loop
        if (i == N_NODES - 1) g_rowptr[N_NODES] = excl + v;
    }
}

__global__ void k_fill(const int* __restrict__ ei) {
    int e = blockIdx.x * blockDim.x + threadIdx.x;
    if (e >= N_EDGES) return;
    unsigned r = (unsigned)ei[e];
    unsigned c = (unsigned)ei[N_EDGES + e];
    if (r >= N_NODES || c >= N_NODES) return;
    int pos = atomicAdd(&g_cursor[c], 1);
    g_srcs[pos] = (int)r;
}

// ---------------- pull propagation: ag1 = A @ x (warp per node, no atomics) ----------------

__global__ void k_prop1(const float* __restrict__ x) {
    int gid = blockIdx.x * blockDim.x + threadIdx.x;
    int n = gid >> 5;
    if (n >= N_NODES) return;
    int l = gid & 31;
    const float4* xp = (const float4*)x;
    float dn = g_dinv[n];
    float s = dn * dn;
    float4 a = xp[(size_t)n * 32 + l];
    float4 acc = make_float4(a.x * s, a.y * s, a.z * s, a.w * s);
    int j = g_rowptr[n], end = g_rowptr[n + 1];
    for (; j + 1 < end; j += 2) {
        int s0 = g_srcs[j], s1 = g_srcs[j + 1];
        float w0 = g_dinv[s0] * dn, w1 = g_dinv[s1] * dn;
        float4 v0 = xp[(size_t)s0 * 32 + l];
        float4 v1 = xp[(size_t)s1 * 32 + l];
        acc.x += w0 * v0.x + w1 * v1.x;
        acc.y += w0 * v0.y + w1 * v1.y;
        acc.z += w0 * v0.z + w1 * v1.z;
        acc.w += w0 * v0.w + w1 * v1.w;
    }
    if (j < end) {
        int s0 = g_srcs[j];
        float w0 = g_dinv[s0] * dn;
        float4 v0 = xp[(size_t)s0 * 32 + l];
        acc.x += w0 * v0.x; acc.y += w0 * v0.y;
        acc.z += w0 * v0.z; acc.w += w0 * v0.w;
    }
    ((float4*)g_ag1)[(size_t)n * 32 + l] = acc;
}

// ---------------- tiled SGEMM core (BM=64, BN=64, BK=64, 256 thr, 4x4 microtile) ----------------

template <int KTOT, int NTOT, bool BIAS, bool RELU>
__device__ __forceinline__ void gemm_core(const float* __restrict__ A,
                                          const float* __restrict__ B,
                                          const float* __restrict__ bias,
                                          float* __restrict__ C, int M) {
    constexpr int BM = 64, BN = 64, BK = 64;
    __shared__ float As[BM][BK];
    __shared__ float Bs[BK][BN];

    int t  = threadIdx.x;       // 256 threads
    int tx = t & 15;
    int ty = t >> 4;
    int m0 = blockIdx.x * BM;
    int n0 = blockIdx.y * BN;

    float acc[4][4] = {};

    for (int kk = 0; kk < KTOT; kk += BK) {
        #pragma unroll
        for (int i = 0; i < 4; i++) {
            int f  = t + i * 256;
            int m  = f >> 4;
            int k4 = f & 15;
            float4 v = make_float4(0.f, 0.f, 0.f, 0.f);
            if (m0 + m < M)
                v = *(const float4*)(A + (size_t)(m0 + m) * KTOT + kk + k4 * 4);
            *(float4*)&As[m][k4 * 4] = v;
        }
        #pragma unroll
        for (int i = 0; i < 4; i++) {
            int f  = t + i * 256;
            int k  = f >> 4;
            int n4 = f & 15;
            float4 v = make_float4(0.f, 0.f, 0.f, 0.f);
            if (n0 + n4 * 4 < NTOT)
                v = *(const float4*)(B + (size_t)(kk + k) * NTOT + n0 + n4 * 4);
            *(float4*)&Bs[k][n4 * 4] = v;
        }
        __syncthreads();

        #pragma unroll
        for (int k = 0; k < BK; k += 4) {
            float4 a[4], b[4];
            #pragma unroll
            for (int i = 0; i < 4; i++) a[i] = *(const float4*)&As[ty * 4 + i][k];
            #pragma unroll
            for (int j = 0; j < 4; j++) b[j] = *(const float4*)&Bs[k + j][tx * 4];
            #pragma unroll
            for (int i = 0; i < 4; i++) {
                const float* av = (const float*)&a[i];
                #pragma unroll
                for (int j = 0; j < 4; j++) {
                    acc[i][j] += av[0] * ((const float*)&b[0])[j];
                    acc[i][j] += av[1] * ((const float*)&b[1])[j];
                    acc[i][j] += av[2] * ((const float*)&b[2])[j];
                    acc[i][j] += av[3] * ((const float*)&b[3])[j];
                }
            }
        }
        __syncthreads();
    }

    #pragma unroll
    for (int i = 0; i < 4; i++) {
        int m = m0 + ty * 4 + i;
        if (m >= M) continue;
        #pragma unroll
        for (int j = 0; j < 4; j++) {
            int n = n0 + tx * 4 + j;
            if (n >= NTOT) continue;
            float v = acc[i][j];
            if (BIAS) v += bias[n];
            if (RELU) v = fmaxf(v, 0.f);
            C[(size_t)m * NTOT + n] = v;
        }
    }
}

__global__ void k_gemm1(const float* __restrict__ W1, const float* __restrict__ b1) {
    gemm_core<F_IN, F_HID, true, true>(g_ag1, W1, b1, g_h, N_NODES);
}

__global__ void k_gemm2(const float* __restrict__ W2) {
    gemm_core<F_HID, F_OUT, false, false>(g_h, W2, nullptr, g_h2, N_NODES);
}

// ---------------- pull propagation: out = A @ h2 + b2 (warp per node) ----------------

__global__ void k_prop2(const float* __restrict__ b2, float* __restrict__ out) {
    int gid = blockIdx.x * blockDim.x + threadIdx.x;
    int n = gid >> 5;
    if (n >= N_NODES) return;
    int l = gid & 31;
    if (l >= 10) return;  // 10 float4 chunks cover 40 feats
    const float4* hp = (const float4*)g_h2;
    float dn = g_dinv[n];
    float s = dn * dn;
    float4 h = hp[(size_t)n * 10 + l];
    float4 b = ((const float4*)b2)[l];
    float4 acc = make_float4(b.x + h.x * s, b.y + h.y * s,
                             b.z + h.z * s, b.w + h.w * s);
    int j = g_rowptr[n], end = g_rowptr[n + 1];
    for (; j + 1 < end; j += 2) {
        int s0 = g_srcs[j], s1 = g_srcs[j + 1];
        float w0 = g_dinv[s0] * dn, w1 = g_dinv[s1] * dn;
        float4 v0 = hp[(size_t)s0 * 10 + l];
        float4 v1 = hp[(size_t)s1 * 10 + l];
        acc.x += w0 * v0.x + w1 * v1.x;
        acc.y += w0 * v0.y + w1 * v1.y;
        acc.z += w0 * v0.z + w1 * v1.z;
        acc.w += w0 * v0.w + w1 * v1.w;
    }
    if (j < end) {
        int s0 = g_srcs[j];
        float w0 = g_dinv[s0] * dn;
        float4 v0 = hp[(size_t)s0 * 10 + l];
        acc.x += w0 * v0.x; acc.y += w0 * v0.y;
        acc.z += w0 * v0.z; acc.w += w0 * v0.w;
    }
    ((float4*)out)[(size_t)n * 10 + l] = acc;
}

// ---------------- launch ----------------

extern "C" void kernel_launch(void* const* d_in, const int* in_sizes, int n_in,
                              void* d_out, int out_size) {
    const float* x  = (const float*)d_in[0];
    const int*   ei = (const int*)d_in[1];
    const float* W1 = (const float*)d_in[2];
    const float* b1 = (const float*)d_in[3];
    const float* W2 = (const float*)d_in[4];
    const float* b2 = (const float*)d_in[5];
    float*       out = (float*)d_out;

    k_zero  <<<(N_NODES + 255) / 256, 256>>>();
    k_count <<<(N_EDGES + 255) / 256, 256>>>(ei);
    k_scan1 <<<NB1, SCAN_B>>>();
    k_scan2 <<<1, 256>>>();
    k_scan3 <<<NB1, SCAN_B>>>();
    k_fill  <<<(N_EDGES + 255) / 256, 256>>>(ei);

    k_prop1 <<<(N_NODES * 32 + 255) / 256, 256>>>(x);

    k_gemm1 <<<dim3((N_NODES + 63) / 64, F_HID / 64), 256>>>(W1, b1);
    k_gemm2 <<<dim3((N_NODES + 63) / 64, 1), 256>>>(W2);

    k_prop2 <<<(N_NODES * 32 + 255) / 256, 256>>>(b2, out);
}

// round 12
// speedup vs baseline: 2.6832x; 1.3995x over previous
#include <cuda_runtime.h>
#include <cuda_bf16.h>

#define N_NODES 100000
#define N_EDGES 1200000
#define F_IN 128
#define F_HID 256
#define F_OUT 40

#define SCAN_B 512
#define NB1 196  // ceil(100000/512)

// Scratch (static device globals — allocation-free per harness rules)
__device__ __align__(16) float g_dinv[N_NODES];
__device__ __align__(16) int   g_cnt[N_NODES];
__device__ __align__(16) int   g_rowptr[N_NODES + 1];
__device__ __align__(16) int   g_cursor[N_NODES];
__device__ __align__(16) int   g_srcs[N_EDGES];
__device__ __align__(16) int   g_blksum[NB1];
__device__ __align__(16) int   g_blkoff[NB1];
__device__ __align__(16) float g_ag1[(size_t)N_NODES * F_IN];   // A @ x
__device__ __align__(16) float g_h  [(size_t)N_NODES * F_HID];  // relu(ag1@W1+b1)
__device__ __align__(16) float g_h2 [(size_t)N_NODES * F_OUT];  // h @ W2

// ---------------- CSR build (counting sort by destination) ----------------

__global__ void k_zero() {
    int i = blockIdx.x * blockDim.x + threadIdx.x;
    if (i < N_NODES) g_cnt[i] = 0;
}

__global__ void k_count(const int* __restrict__ ei) {
    int e = blockIdx.x * blockDim.x + threadIdx.x;
    if (e >= N_EDGES) return;
    unsigned c = (unsigned)ei[N_EDGES + e];
    if (c < N_NODES) atomicAdd(&g_cnt[c], 1);
}

__global__ void k_scan1() {
    __shared__ int sh[SCAN_B / 32];
    int t = threadIdx.x;
    int i = blockIdx.x * SCAN_B + t;
    int v = (i < N_NODES) ? g_cnt[i] : 0;
    #pragma unroll
    for (int o = 16; o; o >>= 1) v += __shfl_down_sync(~0u, v, o);
    if ((t & 31) == 0) sh[t >> 5] = v;
    __syncthreads();
    if (t < SCAN_B / 32) {
        int s = sh[t];
        #pragma unroll
        for (int o = SCAN_B / 64; o; o >>= 1) s += __shfl_down_sync((1u << (SCAN_B / 32)) - 1, s, o);
        if (t == 0) g_blksum[blockIdx.x] = s;
    }
}

__global__ void k_scan2() {
    __shared__ int ws[8];
    int t = threadIdx.x;
    int v = (t < NB1) ? g_blksum[t] : 0;
    int lane = t & 31, w = t >> 5;
    int inc = v;
    #pragma unroll
    for (int o = 1; o < 32; o <<= 1) {
        int u = __shfl_up_sync(~0u, inc, o);
        if (lane >= o) inc += u;
    }
    if (lane == 31) ws[w] = inc;
    __syncthreads();
    if (t < 8) {
        int s = ws[t];
        int i2 = s;
        #pragma unroll
        for (int o = 1; o < 8; o <<= 1) {
            int u = __shfl_up_sync(0xff, i2, o);
            if (t >= o) i2 += u;
        }
        ws[t] = i2 - s;
    }
    __syncthreads();
    if (t < NB1) g_blkoff[t] = inc - v + ws[w];
}

__global__ void k_scan3() {
    __shared__ int ws[SCAN_B / 32];
    int t = threadIdx.x;
    int i = blockIdx.x * SCAN_B + t;
    int v = (i < N_NODES) ? g_cnt[i] : 0;
    int lane = t & 31, w = t >> 5;
    int inc = v;
    #pragma unroll
    for (int o = 1; o < 32; o <<= 1) {
        int u = __shfl_up_sync(~0u, inc, o);
        if (lane >= o) inc += u;
    }
    if (lane == 31) ws[w] = inc;
    __syncthreads();
    if (t < SCAN_B / 32) {
        int s = ws[t];
        int i2 = s;
        #pragma unroll
        for (int o = 1; o < SCAN_B / 32; o <<= 1) {
            int u = __shfl_up_sync((1u << (SCAN_B / 32)) - 1, i2, o);
            if (t >= o) i2 += u;
        }
        ws[t] = i2 - s;
    }
    __syncthreads();
    if (i < N_NODES) {
        int excl = inc - v + ws[w] + g_blkoff[blockIdx.x];
        g_rowptr[i] = excl;
        g_cursor[i] = excl;
        g_dinv[i] = rsqrtf((float)(v + 1));  // +1 self-loop
        if (i == N_NODES - 1) g_rowptr[N_NODES] = excl + v;
    }
}

__global__ void k_fill(const int* __restrict__ ei) {
    int e = blockIdx.x * blockDim.x + threadIdx.x;
    if (e >= N_EDGES) return;
    unsigned r = (unsigned)ei[e];
    unsigned c = (unsigned)ei[N_EDGES + e];
    if (r >= N_NODES || c >= N_NODES) return;
    int pos = atomicAdd(&g_cursor[c], 1);
    g_srcs[pos] = (int)r;
}

// ---------------- pull propagation: ag1 = A @ x (warp per node, no atomics) ----------------

__global__ void k_prop1(const float* __restrict__ x) {
    int gid = blockIdx.x * blockDim.x + threadIdx.x;
    int n = gid >> 5;
    if (n >= N_NODES) return;
    int l = gid & 31;
    const float4* xp = (const float4*)x;
    float dn = g_dinv[n];
    float s = dn * dn;
    float4 a = xp[(size_t)n * 32 + l];
    float4 acc = make_float4(a.x * s, a.y * s, a.z * s, a.w * s);
    int j = g_rowptr[n], end = g_rowptr[n + 1];
    for (; j + 1 < end; j += 2) {
        int s0 = g_srcs[j], s1 = g_srcs[j + 1];
        float w0 = g_dinv[s0] * dn, w1 = g_dinv[s1] * dn;
        float4 v0 = xp[(size_t)s0 * 32 + l];
        float4 v1 = xp[(size_t)s1 * 32 + l];
        acc.x += w0 * v0.x + w1 * v1.x;
        acc.y += w0 * v0.y + w1 * v1.y;
        acc.z += w0 * v0.z + w1 * v1.z;
        acc.w += w0 * v0.w + w1 * v1.w;
    }
    if (j < end) {
        int s0 = g_srcs[j];
        float w0 = g_dinv[s0] * dn;
        float4 v0 = xp[(size_t)s0 * 32 + l];
        acc.x += w0 * v0.x; acc.y += w0 * v0.y;
        acc.z += w0 * v0.z; acc.w += w0 * v0.w;
    }
    ((float4*)g_ag1)[(size_t)n * 32 + l] = acc;
}

// ---------------- bf16x3 tensor-core GEMM ----------------
// C = A@B (+bias)(+relu), fp32 in/out. Split x = hi + lo (bf16 each);
// A*B ~= Ah*Bh + Al*Bh + Ah*Bl  (error ~2^-16 rel).

__device__ __forceinline__ void ldmA(unsigned& r0, unsigned& r1, unsigned& r2, unsigned& r3,
                                     unsigned addr) {
    asm volatile("ldmatrix.sync.aligned.m8n8.x4.shared.b16 {%0,%1,%2,%3}, [%4];"
                 : "=r"(r0), "=r"(r1), "=r"(r2), "=r"(r3) : "r"(addr));
}
__device__ __forceinline__ void ldmBT(unsigned& r0, unsigned& r1, unsigned& r2, unsigned& r3,
                                      unsigned addr) {
    asm volatile("ldmatrix.sync.aligned.m8n8.x4.trans.shared.b16 {%0,%1,%2,%3}, [%4];"
                 : "=r"(r0), "=r"(r1), "=r"(r2), "=r"(r3) : "r"(addr));
}
__device__ __forceinline__ void mma_bf16(float c[4], const unsigned a[4], const unsigned* b) {
    asm volatile("mma.sync.aligned.m16n8k16.row.col.f32.bf16.bf16.f32 "
                 "{%0,%1,%2,%3},{%4,%5,%6,%7},{%8,%9},{%0,%1,%2,%3};"
                 : "+f"(c[0]), "+f"(c[1]), "+f"(c[2]), "+f"(c[3])
                 : "r"(a[0]), "r"(a[1]), "r"(a[2]), "r"(a[3]), "r"(b[0]), "r"(b[1]));
}

// BM=128, BN=64, BK=32. 256 threads = 8 warps (4 M x 2 N), warp tile 32x32.
template <int KTOT, int NTOT, bool BIAS, bool RELU>
__device__ __forceinline__ void tc_gemm(const float* __restrict__ A,
                                        const float* __restrict__ B,
                                        const float* __restrict__ bias,
                                        float* __restrict__ C, int M) {
    constexpr int BM = 128, BN = 64, BK = 32;
    constexpr int ASTR = BK + 8;  // 40 halves -> conflict-free ldmatrix
    constexpr int BSTR = BN + 8;  // 72 halves -> conflict-free ldmatrix.trans
    __shared__ __nv_bfloat16 Ah[BM * ASTR], Al[BM * ASTR];
    __shared__ __nv_bfloat16 Bh[BK * BSTR], Bl[BK * BSTR];

    const int t = threadIdx.x, lane = t & 31, wid = t >> 5;
    const int wm = wid & 3, wn = wid >> 2;
    const int m0 = blockIdx.x * BM, n0 = blockIdx.y * BN;

    const unsigned ah_base = (unsigned)__cvta_generic_to_shared(Ah);
    const unsigned al_base = (unsigned)__cvta_generic_to_shared(Al);
    const unsigned bh_base = (unsigned)__cvta_generic_to_shared(Bh);
    const unsigned bl_base = (unsigned)__cvta_generic_to_shared(Bl);

    float c[2][4][4] = {};

    for (int kk = 0; kk < KTOT; kk += BK) {
        // stage A tile 128x32: 4096 floats, 16/thread (4 float4)
        #pragma unroll
        for (int i = 0; i < 4; i++) {
            int f = t + i * 256;
            int m = f >> 3, c4 = f & 7;
            float4 v = make_float4(0.f, 0.f, 0.f, 0.f);
            if (m0 + m < M)
                v = *(const float4*)(A + (size_t)(m0 + m) * KTOT + kk + c4 * 4);
            int p = m * ASTR + c4 * 4;
            const float* vv = (const float*)&v;
            #pragma unroll
            for (int j = 0; j < 4; j++) {
                __nv_bfloat16 h = __float2bfloat16_rn(vv[j]);
                Ah[p + j] = h;
                Al[p + j] = __float2bfloat16_rn(vv[j] - __bfloat162float(h));
            }
        }
        // stage B tile 32x64: 2048 floats, 8/thread (2 float4)
        #pragma unroll
        for (int i = 0; i < 2; i++) {
            int f = t + i * 256;
            int k = f >> 4, c4 = f & 15;
            float4 v = make_float4(0.f, 0.f, 0.f, 0.f);
            if (n0 + c4 * 4 + 3 < NTOT)
                v = *(const float4*)(B + (size_t)(kk + k) * NTOT + n0 + c4 * 4);
            int p = k * BSTR + c4 * 4;
            const float* vv = (const float*)&v;
            #pragma unroll
            for (int j = 0; j < 4; j++) {
                __nv_bfloat16 h = __float2bfloat16_rn(vv[j]);
                Bh[p + j] = h;
                Bl[p + j] = __float2bfloat16_rn(vv[j] - __bfloat162float(h));
            }
        }
        __syncthreads();

        #pragma unroll
        for (int ks = 0; ks < 2; ks++) {  // two k16 steps
            const int kb = ks * 16;
            // A frags: rows wm*32 + i*16 + (lane&15), halves col kb + (lane>>4)*8
            unsigned ahr[2][4], alr[2][4];
            #pragma unroll
            for (int i = 0; i < 2; i++) {
                unsigned off = ((wm * 32 + i * 16 + (lane & 15)) * ASTR
                                + kb + ((lane >> 4) << 3)) * 2;
                ldmA(ahr[i][0], ahr[i][1], ahr[i][2], ahr[i][3], ah_base + off);
                ldmA(alr[i][0], alr[i][1], alr[i][2], alr[i][3], al_base + off);
            }
            // B frags: x4.trans covers n16 (2 n-frags): row k = kb + (l&7) + (l&8),
            // col = nb + ((l>>4)*8)
            unsigned bhr[4][2], blr[4][2];
            #pragma unroll
            for (int j = 0; j < 2; j++) {
                int nb = wn * 32 + j * 16;
                unsigned off = ((kb + (lane & 7) + (lane & 8)) * BSTR
                                + nb + ((lane >> 4) << 3)) * 2;
                unsigned r0, r1, r2, r3;
                ldmBT(r0, r1, r2, r3, bh_base + off);
                bhr[j * 2][0] = r0; bhr[j * 2][1] = r1;
                bhr[j * 2 + 1][0] = r2; bhr[j * 2 + 1][1] = r3;
                ldmBT(r0, r1, r2, r3, bl_base + off);
                blr[j * 2][0] = r0; blr[j * 2][1] = r1;
                blr[j * 2 + 1][0] = r2; blr[j * 2 + 1][1] = r3;
            }
            #pragma unroll
            for (int i = 0; i < 2; i++)
                #pragma unroll
                for (int f = 0; f < 4; f++) {
                    mma_bf16(c[i][f], ahr[i], bhr[f]);
                    mma_bf16(c[i][f], alr[i], bhr[f]);
                    mma_bf16(c[i][f], ahr[i], blr[f]);
                }
        }
        __syncthreads();
    }

    // epilogue: lane g=l>>2 rows, 2*(l&3) col pair; c0,c1 row g; c2,c3 row g+8
    const int g = lane >> 2, tp = lane & 3;
    #pragma unroll
    for (int i = 0; i < 2; i++) {
        int r0 = m0 + wm * 32 + i * 16 + g;
        #pragma unroll
        for (int f = 0; f < 4; f++) {
            int col = n0 + wn * 32 + f * 8 + 2 * tp;
            if (col + 1 < NTOT || col + 1 == NTOT - 0) {}  // no-op; real guard below
            if (col < NTOT) {
                float b0 = 0.f, b1 = 0.f;
                if (BIAS) { b0 = bias[col]; b1 = bias[col + 1]; }
                float v0 = c[i][f][0] + b0, v1 = c[i][f][1] + b1;
                float v2 = c[i][f][2] + b0, v3 = c[i][f][3] + b1;
                if (RELU) {
                    v0 = fmaxf(v0, 0.f); v1 = fmaxf(v1, 0.f);
                    v2 = fmaxf(v2, 0.f); v3 = fmaxf(v3, 0.f);
                }
                if (r0 < M)     *(float2*)(C + (size_t)r0 * NTOT + col) = make_float2(v0, v1);
                if (r0 + 8 < M) *(float2*)(C + (size_t)(r0 + 8) * NTOT + col) = make_float2(v2, v3);
            }
        }
    }
}

__global__ void k_gemm1(const float* __restrict__ W1, const float* __restrict__ b1) {
    tc_gemm<F_IN, F_HID, true, true>(g_ag1, W1, b1, g_h, N_NODES);
}

__global__ void k_gemm2(const float* __restrict__ W2) {
    tc_gemm<F_HID, F_OUT, false, false>(g_h, W2, nullptr, g_h2, N_NODES);
}

// ---------------- pull propagation: out = A @ h2 + b2 (warp per node) ----------------

__global__ void k_prop2(const float* __restrict__ b2, float* __restrict__ out) {
    int gid = blockIdx.x * blockDim.x + threadIdx.x;
    int n = gid >> 5;
    if (n >= N_NODES) return;
    int l = gid & 31;
    if (l >= 10) return;  // 10 float4 chunks cover 40 feats
    const float4* hp = (const float4*)g_h2;
    float dn = g_dinv[n];
    float s = dn * dn;
    float4 h = hp[(size_t)n * 10 + l];
    float4 b = ((const float4*)b2)[l];
    float4 acc = make_float4(b.x + h.x * s, b.y + h.y * s,
                             b.z + h.z * s, b.w + h.w * s);
    int j = g_rowptr[n], end = g_rowptr[n + 1];
    for (; j + 1 < end; j += 2) {
        int s0 = g_srcs[j], s1 = g_srcs[j + 1];
        float w0 = g_dinv[s0] * dn, w1 = g_dinv[s1] * dn;
        float4 v0 = hp[(size_t)s0 * 10 + l];
        float4 v1 = hp[(size_t)s1 * 10 + l];
        acc.x += w0 * v0.x + w1 * v1.x;
        acc.y += w0 * v0.y + w1 * v1.y;
        acc.z += w0 * v0.z + w1 * v1.z;
        acc.w += w0 * v0.w + w1 * v1.w;
    }
    if (j < end) {
        int s0 = g_srcs[j];
        float w0 = g_dinv[s0] * dn;
        float4 v0 = hp[(size_t)s0 * 10 + l];
        acc.x += w0 * v0.x; acc.y += w0 * v0.y;
        acc.z += w0 * v0.z; acc.w += w0 * v0.w;
    }
    ((float4*)out)[(size_t)n * 10 + l] = acc;
}

// ---------------- launch ----------------

extern "C" void kernel_launch(void* const* d_in, const int* in_sizes, int n_in,
                              void* d_out, int out_size) {
    const float* x  = (const float*)d_in[0];
    const int*   ei = (const int*)d_in[1];
    const float* W1 = (const float*)d_in[2];
    const float* b1 = (const float*)d_in[3];
    const float* W2 = (const float*)d_in[4];
    const float* b2 = (const float*)d_in[5];
    float*       out = (float*)d_out;

    k_zero  <<<(N_NODES + 255) / 256, 256>>>();
    k_count <<<(N_EDGES + 255) / 256, 256>>>(ei);
    k_scan1 <<<NB1, SCAN_B>>>();
    k_scan2 <<<1, 256>>>();
    k_scan3 <<<NB1, SCAN_B>>>();
    k_fill  <<<(N_EDGES + 255) / 256, 256>>>(ei);

    k_prop1 <<<(N_NODES * 32 + 255) / 256, 256>>>(x);

    k_gemm1 <<<dim3((N_NODES + 127) / 128, F_HID / 64), 256>>>(W1, b1);
    k_gemm2 <<<dim3((N_NODES + 127) / 128, 1), 256>>>(W2);

    k_prop2 <<<(N_NODES * 32 + 255) / 256, 256>>>(b2, out);
}

// round 17
// speedup vs baseline: 2.8291x; 1.0544x over previous
#include <cuda_runtime.h>
#include <cuda_bf16.h>

#define N_NODES 100000
#define N_EDGES 1200000
#define F_IN 128
#define F_HID 256
#define F_OUT 40

#define SCAN_B 512
#define NB1 196  // ceil(100000/512)

// Scratch (static device globals — allocation-free per harness rules)
__device__ __align__(16) float g_dinv[N_NODES];
__device__ __align__(16) int   g_cnt[N_NODES];
__device__ __align__(16) int   g_rowptr[N_NODES + 1];
__device__ __align__(16) int   g_cursor[N_NODES];
__device__ __align__(16) int   g_srcs[N_EDGES];
__device__ __align__(16) int   g_blksum[NB1];
__device__ __align__(16) float g_ag1[(size_t)N_NODES * F_IN];   // A @ x
__device__ __align__(16) float g_h  [(size_t)N_NODES * F_HID];  // relu(ag1@W1+b1)
__device__ __align__(16) float g_h2 [(size_t)N_NODES * F_OUT];  // h @ W2

// ---------------- CSR build (counting sort by destination) ----------------

__global__ void k_zero() {
    int i = blockIdx.x * blockDim.x + threadIdx.x;
    if (i < N_NODES) g_cnt[i] = 0;
}

__global__ void k_count(const int* __restrict__ ei) {
    int e = blockIdx.x * blockDim.x + threadIdx.x;
    if (e >= N_EDGES) return;
    unsigned c = (unsigned)ei[N_EDGES + e];
    if (c < N_NODES) atomicAdd(&g_cnt[c], 1);
}

__global__ void k_scan1() {
    __shared__ int sh[SCAN_B / 32];
    int t = threadIdx.x;
    int i = blockIdx.x * SCAN_B + t;
    int v = (i < N_NODES) ? g_cnt[i] : 0;
    #pragma unroll
    for (int o = 16; o; o >>= 1) v += __shfl_down_sync(~0u, v, o);
    if ((t & 31) == 0) sh[t >> 5] = v;
    __syncthreads();
    if (t < SCAN_B / 32) {
        int s = sh[t];
        #pragma unroll
        for (int o = SCAN_B / 64; o; o >>= 1) s += __shfl_down_sync((1u << (SCAN_B / 32)) - 1, s, o);
        if (t == 0) g_blksum[blockIdx.x] = s;
    }
}

// local exclusive scan + self-computed global block offset -> rowptr, cursor, dinv
__global__ void k_scan3() {
    __shared__ int ws[SCAN_B / 32];
    __shared__ int blkoff_sh;
    int t = threadIdx.x;
    int i = blockIdx.x * SCAN_B + t;
    int v = (i < N_NODES) ? g_cnt[i] : 0;
    int lane = t & 31, w = t >> 5;
    int inc = v;
    #pragma unroll
    for (int o = 1; o < 32; o <<= 1) {
        int u = __shfl_up_sync(~0u, inc, o);
        if (lane >= o) inc += u;
    }
    if (lane == 31) ws[w] = inc;
    __syncthreads();
    // warp 0: scan of per-warp sums; warp 1: prefix over preceding blocks' sums
    if (t < SCAN_B / 32) {
        int s = ws[t];
        int i2 = s;
        #pragma unroll
        for (int o = 1; o < SCAN_B / 32; o <<= 1) {
            int u = __shfl_up_sync((1u << (SCAN_B / 32)) - 1, i2, o);
            if (t >= o) i2 += u;
        }
        ws[t] = i2 - s;
    } else if (t >= 32 && t < 64) {
        int s = 0;
        for (int b = t - 32; b < blockIdx.x; b += 32) s += g_blksum[b];
        #pragma unroll
        for (int o = 16; o; o >>= 1) s += __shfl_down_sync(~0u, s, o);
        if (t == 32) blkoff_sh = s;
    }
    __syncthreads();
    if (i < N_NODES) {
        int excl = inc - v + ws[w] + blkoff_sh;
        g_rowptr[i] = excl;
        g_cursor[i] = excl;
        g_dinv[i] = rsqrtf((float)(v + 1));  // +1 self-loop
        if (i == N_NODES - 1) g_rowptr[N_NODES] = excl + v;
    }
}

__global__ void k_fill(const int* __restrict__ ei) {
    int e = blockIdx.x * blockDim.x + threadIdx.x;
    if (e >= N_EDGES) return;
    unsigned r = (unsigned)ei[e];
    unsigned c = (unsigned)ei[N_EDGES + e];
    if (r >= N_NODES || c >= N_NODES) return;
    int pos = atomicAdd(&g_cursor[c], 1);
    g_srcs[pos] = (int)r;
}

// ---------------- pull propagation: ag1 = A @ x (warp per node, no atomics) ----------------

__global__ void k_prop1(const float* __restrict__ x) {
    int gid = blockIdx.x * blockDim.x + threadIdx.x;
    int n = gid >> 5;
    if (n >= N_NODES) return;
    int l = gid & 31;
    const float4* xp = (const float4*)x;
    float dn = g_dinv[n];
    float s = dn * dn;
    float4 a = xp[(size_t)n * 32 + l];
    float4 acc = make_float4(a.x * s, a.y * s, a.z * s, a.w * s);
    int j = g_rowptr[n], end = g_rowptr[n + 1];
    for (; j + 1 < end; j += 2) {
        int s0 = g_srcs[j], s1 = g_srcs[j + 1];
        float w0 = g_dinv[s0] * dn, w1 = g_dinv[s1] * dn;
        float4 v0 = xp[(size_t)s0 * 32 + l];
        float4 v1 = xp[(size_t)s1 * 32 + l];
        acc.x += w0 * v0.x + w1 * v1.x;
        acc.y += w0 * v0.y + w1 * v1.y;
        acc.z += w0 * v0.z + w1 * v1.z;
        acc.w += w0 * v0.w + w1 * v1.w;
    }
    if (j < end) {
        int s0 = g_srcs[j];
        float w0 = g_dinv[s0] * dn;
        float4 v0 = xp[(size_t)s0 * 32 + l];
        acc.x += w0 * v0.x; acc.y += w0 * v0.y;
        acc.z += w0 * v0.z; acc.w += w0 * v0.w;
    }
    ((float4*)g_ag1)[(size_t)n * 32 + l] = acc;
}

// ---------------- bf16x3 tensor-core GEMM ----------------
// C = A@B (+bias)(+relu), fp32 in/out. Split x = hi + lo (bf16 each);
// A*B ~= Ah*Bh + Al*Bh + Ah*Bl  (error ~2^-16 rel).

__device__ __forceinline__ void ldmA(unsigned& r0, unsigned& r1, unsigned& r2, unsigned& r3,
                                     unsigned addr) {
    asm volatile("ldmatrix.sync.aligned.m8n8.x4.shared.b16 {%0,%1,%2,%3}, [%4];"
                 : "=r"(r0), "=r"(r1), "=r"(r2), "=r"(r3) : "r"(addr));
}
__device__ __forceinline__ void ldmBT(unsigned& r0, unsigned& r1, unsigned& r2, unsigned& r3,
                                      unsigned addr) {
    asm volatile("ldmatrix.sync.aligned.m8n8.x4.trans.shared.b16 {%0,%1,%2,%3}, [%4];"
                 : "=r"(r0), "=r"(r1), "=r"(r2), "=r"(r3) : "r"(addr));
}
__device__ __forceinline__ void mma_bf16(float c[4], const unsigned a[4], const unsigned* b) {
    asm volatile("mma.sync.aligned.m16n8k16.row.col.f32.bf16.bf16.f32 "
                 "{%0,%1,%2,%3},{%4,%5,%6,%7},{%8,%9},{%0,%1,%2,%3};"
                 : "+f"(c[0]), "+f"(c[1]), "+f"(c[2]), "+f"(c[3])
                 : "r"(a[0]), "r"(a[1]), "r"(a[2]), "r"(a[3]), "r"(b[0]), "r"(b[1]));
}

// BM=128, BN=64, BK=32. 256 threads = 8 warps (4 M x 2 N), warp tile 32x32.
// Register prefetch: next k-tile's global loads overlap current tile's MMAs.
template <int KTOT, int NTOT, bool BIAS, bool RELU>
__device__ __forceinline__ void tc_gemm(const float* __restrict__ A,
                                        const float* __restrict__ B,
                                        const float* __restrict__ bias,
                                        float* __restrict__ C, int M) {
    constexpr int BM = 128, BN = 64, BK = 32;
    constexpr int ASTR = BK + 8;  // 40 halves -> conflict-free ldmatrix
    constexpr int BSTR = BN + 8;  // 72 halves -> conflict-free ldmatrix.trans
    constexpr int NITER = KTOT / BK;
    __shared__ __nv_bfloat16 Ah[BM * ASTR], Al[BM * ASTR];
    __shared__ __nv_bfloat16 Bh[BK * BSTR], Bl[BK * BSTR];

    const int t = threadIdx.x, lane = t & 31, wid = t >> 5;
    const int wm = wid & 3, wn = wid >> 2;
    const int m0 = blockIdx.x * BM, n0 = blockIdx.y * BN;

    const unsigned ah_base = (unsigned)__cvta_generic_to_shared(Ah);
    const unsigned al_base = (unsigned)__cvta_generic_to_shared(Al);
    const unsigned bh_base = (unsigned)__cvta_generic_to_shared(Bh);
    const unsigned bl_base = (unsigned)__cvta_generic_to_shared(Bl);

    float c[2][4][4] = {};
    float4 pa[4], pb[2];

    // prefetch tile 0
    #pragma unroll
    for (int i = 0; i < 4; i++) {
        int f = t + i * 256;
        int m = f >> 3, c4 = f & 7;
        pa[i] = make_float4(0.f, 0.f, 0.f, 0.f);
        if (m0 + m < M)
            pa[i] = *(const float4*)(A + (size_t)(m0 + m) * KTOT + c4 * 4);
    }
    #pragma unroll
    for (int i = 0; i < 2; i++) {
        int f = t + i * 256;
        int k = f >> 4, c4 = f & 15;
        pb[i] = make_float4(0.f, 0.f, 0.f, 0.f);
        if (n0 + c4 * 4 + 3 < NTOT)
            pb[i] = *(const float4*)(B + (size_t)k * NTOT + n0 + c4 * 4);
    }

    for (int it = 0; it < NITER; it++) {
        // convert + store staged regs to smem
        #pragma unroll
        for (int i = 0; i < 4; i++) {
            int f = t + i * 256;
            int m = f >> 3, c4 = f & 7;
            int p = m * ASTR + c4 * 4;
            const float* vv = (const float*)&pa[i];
            #pragma unroll
            for (int j = 0; j < 4; j++) {
                __nv_bfloat16 h = __float2bfloat16_rn(vv[j]);
                Ah[p + j] = h;
                Al[p + j] = __float2bfloat16_rn(vv[j] - __bfloat162float(h));
            }
        }
        #pragma unroll
        for (int i = 0; i < 2; i++) {
            int f = t + i * 256;
            int k = f >> 4, c4 = f & 15;
            int p = k * BSTR + c4 * 4;
            const float* vv = (const float*)&pb[i];
            #pragma unroll
            for (int j = 0; j < 4; j++) {
                __nv_bfloat16 h = __float2bfloat16_rn(vv[j]);
                Bh[p + j] = h;
                Bl[p + j] = __float2bfloat16_rn(vv[j] - __bfloat162float(h));
            }
        }
        __syncthreads();

        // prefetch next tile while MMAs run
        if (it + 1 < NITER) {
            const int kk = (it + 1) * BK;
            #pragma unroll
            for (int i = 0; i < 4; i++) {
                int f = t + i * 256;
                int m = f >> 3, c4 = f & 7;
                pa[i] = make_float4(0.f, 0.f, 0.f, 0.f);
                if (m0 + m < M)
                    pa[i] = *(const float4*)(A + (size_t)(m0 + m) * KTOT + kk + c4 * 4);
            }
            #pragma unroll
            for (int i = 0; i < 2; i++) {
                int f = t + i * 256;
                int k = f >> 4, c4 = f & 15;
                pb[i] = make_float4(0.f, 0.f, 0.f, 0.f);
                if (n0 + c4 * 4 + 3 < NTOT)
                    pb[i] = *(const float4*)(B + (size_t)(kk + k) * NTOT + n0 + c4 * 4);
            }
        }

        #pragma unroll
        for (int ks = 0; ks < 2; ks++) {  // two k16 steps
            const int kb = ks * 16;
            unsigned ahr[2][4], alr[2][4];
            #pragma unroll
            for (int i = 0; i < 2; i++) {
                unsigned off = ((wm * 32 + i * 16 + (lane & 15)) * ASTR
                                + kb + ((lane >> 4) << 3)) * 2;
                ldmA(ahr[i][0], ahr[i][1], ahr[i][2], ahr[i][3], ah_base + off);
                ldmA(alr[i][0], alr[i][1], alr[i][2], alr[i][3], al_base + off);
            }
            unsigned bhr[4][2], blr[4][2];
            #pragma unroll
            for (int j = 0; j < 2; j++) {
                int nb = wn * 32 + j * 16;
                unsigned off = ((kb + (lane & 7) + (lane & 8)) * BSTR
                                + nb + ((lane >> 4) << 3)) * 2;
                unsigned r0, r1, r2, r3;
                ldmBT(r0, r1, r2, r3, bh_base + off);
                bhr[j * 2][0] = r0; bhr[j * 2][1] = r1;
                bhr[j * 2 + 1][0] = r2; bhr[j * 2 + 1][1] = r3;
                ldmBT(r0, r1, r2, r3, bl_base + off);
                blr[j * 2][0] = r0; blr[j * 2][1] = r1;
                blr[j * 2 + 1][0] = r2; blr[j * 2 + 1][1] = r3;
            }
            #pragma unroll
            for (int i = 0; i < 2; i++)
                #pragma unroll
                for (int f = 0; f < 4; f++) {
                    mma_bf16(c[i][f], ahr[i], bhr[f]);
                    mma_bf16(c[i][f], alr[i], bhr[f]);
                    mma_bf16(c[i][f], ahr[i], blr[f]);
                }
        }
        __syncthreads();
    }

    // epilogue: lane g=l>>2 rows, 2*(l&3) col pair; c0,c1 row g; c2,c3 row g+8
    const int g = lane >> 2, tp = lane & 3;
    #pragma unroll
    for (int i = 0; i < 2; i++) {
        int r0 = m0 + wm * 32 + i * 16 + g;
        #pragma unroll
        for (int f = 0; f < 4; f++) {
            int col = n0 + wn * 32 + f * 8 + 2 * tp;
            if (col < NTOT) {
                float b0 = 0.f, b1 = 0.f;
                if (BIAS) { b0 = bias[col]; b1 = bias[col + 1]; }
                float v0 = c[i][f][0] + b0, v1 = c[i][f][1] + b1;
                float v2 = c[i][f][2] + b0, v3 = c[i][f][3] + b1;
                if (RELU) {
                    v0 = fmaxf(v0, 0.f); v1 = fmaxf(v1, 0.f);
                    v2 = fmaxf(v2, 0.f); v3 = fmaxf(v3, 0.f);
                }
                if (r0 < M)     *(float2*)(C + (size_t)r0 * NTOT + col) = make_float2(v0, v1);
                if (r0 + 8 < M) *(float2*)(C + (size_t)(r0 + 8) * NTOT + col) = make_float2(v2, v3);
            }
        }
    }
}

__global__ void k_gemm1(const float* __restrict__ W1, const float* __restrict__ b1) {
    tc_gemm<F_IN, F_HID, true, true>(g_ag1, W1, b1, g_h, N_NODES);
}

__global__ void k_gemm2(const float* __restrict__ W2) {
    tc_gemm<F_HID, F_OUT, false, false>(g_h, W2, nullptr, g_h2, N_NODES);
}

// ---------------- pull propagation: out = A @ h2 + b2 (3 nodes per warp) ----------------

__global__ void k_prop2(const float* __restrict__ b2, float* __restrict__ out) {
    int gid = blockIdx.x * blockDim.x + threadIdx.x;
    int warp = gid >> 5;
    int lane = gid & 31;
    int sub = lane / 10;          // 0..2 (lanes 30,31 idle)
    int l   = lane - sub * 10;    // chunk 0..9
    int n = warp * 3 + sub;
    if (sub >= 3 || n >= N_NODES) return;
    const float4* hp = (const float4*)g_h2;
    float dn = g_dinv[n];
    float s = dn * dn;
    float4 h = hp[(size_t)n * 10 + l];
    float4 b = ((const float4*)b2)[l];
    float4 acc = make_float4(b.x + h.x * s, b.y + h.y * s,
                             b.z + h.z * s, b.w + h.w * s);
    int j = g_rowptr[n], end = g_rowptr[n + 1];
    for (; j + 1 < end; j += 2) {
        int s0 = g_srcs[j], s1 = g_srcs[j + 1];
        float w0 = g_dinv[s0] * dn, w1 = g_dinv[s1] * dn;
        float4 v0 = hp[(size_t)s0 * 10 + l];
        float4 v1 = hp[(size_t)s1 * 10 + l];
        acc.x += w0 * v0.x + w1 * v1.x;
        acc.y += w0 * v0.y + w1 * v1.y;
        acc.z += w0 * v0.z + w1 * v1.z;
        acc.w += w0 * v0.w + w1 * v1.w;
    }
    if (j < end) {
        int s0 = g_srcs[j];
        float w0 = g_dinv[s0] * dn;
        float4 v0 = hp[(size_t)s0 * 10 + l];
        acc.x += w0 * v0.x; acc.y += w0 * v0.y;
        acc.z += w0 * v0.z; acc.w += w0 * v0.w;
    }
    ((float4*)out)[(size_t)n * 10 + l] = acc;
}

// ---------------- launch ----------------

extern "C" void kernel_launch(void* const* d_in, const int* in_sizes, int n_in,
                              void* d_out, int out_size) {
    const float* x  = (const float*)d_in[0];
    const int*   ei = (const int*)d_in[1];
    const float* W1 = (const float*)d_in[2];
    const float* b1 = (const float*)d_in[3];
    const float* W2 = (const float*)d_in[4];
    const float* b2 = (const float*)d_in[5];
    float*       out = (float*)d_out;

    k_zero  <<<(N_NODES + 255) / 256, 256>>>();
    k_count <<<(N_EDGES + 255) / 256, 256>>>(ei);
    k_scan1 <<<NB1, SCAN_B>>>();
    k_scan3 <<<NB1, SCAN_B>>>();
    k_fill  <<<(N_EDGES + 255) / 256, 256>>>(ei);

    k_prop1 <<<(N_NODES * 32 + 255) / 256, 256>>>(x);

    k_gemm1 <<<dim3((N_NODES + 127) / 128, F_HID / 64), 256>>>(W1, b1);
    k_gemm2 <<<dim3((N_NODES + 127) / 128, 1), 256>>>(W2);

    int nwarps2 = (N_NODES + 2) / 3;
    k_prop2 <<<(nwarps2 * 32 + 255) / 256, 256>>>(b2, out);
}